// round 12
// baseline (speedup 1.0000x reference)
#include <cuda_runtime.h>
#include <cuda_fp16.h>
#include <cstdint>
#include <cstddef>

// Problem constants
#define B_  1024
#define T_  85
#define F_  36
#define H_  512
#define C_  69

#define ASTR 40        // general kernel: halfs per smem row (32 data + 8 pad)
#define BK 32
#define STAGES 3

// ---------------------------------------------------------------------------
// Device globals
// ---------------------------------------------------------------------------
__device__ __half g_hA[B_ * 4 * H_];
__device__ __half g_hB[B_ * 4 * H_];
__device__ __half g_hC[B_ * H_];                        // h25 (init 512-wide)
__device__ __half g_S[(size_t)(T_ - 1) * B_ * H_];      // all s_t (fp16)
__device__ __half g_srch[B_ * 3072];
__device__ float  g_bc[C_];                             // composed out bias
__device__ float  g_bb[2048];                           // bc @ W1c
__device__ float  g_bbi[2048];                          // bi3 @ W1c
__device__ float  g_w4c32[H_ * C_];                     // w4@w4d fp32
__device__ float  g_P[(size_t)(T_ - 1) * B_ * 2048];    // layer-1 partial (incl b1)

// fp16 K-major weights [N][Kp], packed (offsets in halfs)
#define OFF_WI1T    0u          /* 2048 x 3072 */
#define OFF_WI2T    6291456u    /* 1024 x 2048 */
#define OFF_WI25T   8388608u    /* 512  x 1024 */
#define OFF_WI3T    8912896u    /* 69   x 512  */
#define OFF_W1ABT   8948224u    /* 2048 x 96   */
#define OFF_W12T    9144832u    /* 2048 x 2048 */
#define OFF_W2T     13339136u   /* 1024 x 2048 */
#define OFF_W22T    15436288u   /* 1024 x 1024 */
#define OFF_W3T     16484864u   /* 512  x 1024 */
#define OFF_W4CT    17009152u   /* 69   x 512  */
#define OFF_W41T    17044480u   /* 2048 x 512  */
#define OFF_WI31T   18093056u   /* 2048 x 512  */
#define WH_TOTAL    19141632u
__device__ __half g_wh[WH_TOTAL];

// ---------------------------------------------------------------------------
__device__ __forceinline__ uint32_t smem_u32(const void* p) {
    return (uint32_t)__cvta_generic_to_shared(p);
}

__device__ __forceinline__ void mma_f16(float (&d)[4],
                                        const uint32_t (&a)[4],
                                        const uint32_t (&b)[2]) {
    asm volatile(
        "mma.sync.aligned.m16n8k16.row.col.f32.f16.f16.f32 "
        "{%0,%1,%2,%3}, {%4,%5,%6,%7}, {%8,%9}, {%0,%1,%2,%3};"
        : "+f"(d[0]), "+f"(d[1]), "+f"(d[2]), "+f"(d[3])
        : "r"(a[0]), "r"(a[1]), "r"(a[2]), "r"(a[3]),
          "r"(b[0]), "r"(b[1]));
}

__device__ __forceinline__ void ldsm_x4(uint32_t (&r)[4], uint32_t addr) {
    asm volatile(
        "ldmatrix.sync.aligned.m8n8.x4.shared.b16 {%0,%1,%2,%3}, [%4];"
        : "=r"(r[0]), "=r"(r[1]), "=r"(r[2]), "=r"(r[3]) : "r"(addr));
}

// ---------------------------------------------------------------------------
// Scan-layer GEMM (fast path, R9 core): M = 1024 fixed, exact tiling, BK=64.
// C[1024,N] = relu(A[1024,K] @ Wt[N,K]^T + bias [+ addin]), fp16 out, ldc=N.
// ---------------------------------------------------------------------------
template<int BM, int BN, int NSTG>
__global__ __launch_bounds__(256, 2)
void scan_gemm(const __half* __restrict__ A,
               const __half* __restrict__ Wt,
               const float* __restrict__ bias,
               __half* __restrict__ Cout,
               int N, int K,
               const float* __restrict__ addin)
{
    constexpr int RSTR = 72;       // 64 data + 8 pad halfs
    constexpr int MT = BM / 32;
    constexpr int NT = BN / 32;
    constexpr int WG = NSTG - 2;   // wait_group depth

    extern __shared__ __align__(16) char smem_raw[];
    __half* Asm = (__half*)smem_raw;
    __half* Bsm = Asm + NSTG * BM * RSTR;

    const int bm   = blockIdx.y * BM;
    const int bn   = blockIdx.x * BN;
    const int tid  = threadIdx.x;
    const int lane = tid & 31;
    const int wid  = tid >> 5;
    const int warpM = wid >> 2;
    const int warpN = wid & 3;
    const int gp = lane >> 2;
    const int lq = lane & 3;

    const int KT = K >> 6;         // K / 64

    auto fetchA = [&](int st, int kt) {
#pragma unroll
        for (int i = 0; i < BM / 32; i++) {
            int c   = i * 256 + tid;
            int row = c >> 3;
            int ch  = c & 7;
            const __half* g = A + (size_t)(bm + row) * K + kt * 64 + ch * 8;
            uint32_t dst = smem_u32(Asm + (st * BM + row) * RSTR + ch * 8);
            asm volatile("cp.async.ca.shared.global [%0], [%1], 16;"
                         :: "r"(dst), "l"(g));
        }
    };
    auto fetchB = [&](int st, int kt) {
#pragma unroll
        for (int i = 0; i < BN / 32; i++) {
            int c   = i * 256 + tid;
            int row = c >> 3;
            int ch  = c & 7;
            const __half* g = Wt + (size_t)(bn + row) * K + kt * 64 + ch * 8;
            uint32_t dst = smem_u32(Bsm + (st * BN + row) * RSTR + ch * 8);
            asm volatile("cp.async.ca.shared.global [%0], [%1], 16;"
                         :: "r"(dst), "l"(g));
        }
    };

    float acc[MT][NT][4];
#pragma unroll
    for (int i = 0; i < MT; i++)
#pragma unroll
        for (int j = 0; j < NT; j++)
#pragma unroll
            for (int v = 0; v < 4; v++) acc[i][j][v] = 0.f;

#pragma unroll
    for (int s = 0; s < NSTG - 1; s++) {
        if (s < KT) { fetchA(s, s); fetchB(s, s); }
        asm volatile("cp.async.commit_group;" ::: "memory");
    }

    const int aRowSel = lane & 15;
    const int aColSel = (lane >> 4) << 3;
    const int bRowSel = ((lane >> 4) << 3) + (lane & 7);
    const int bColSel = ((lane >> 3) & 1) << 3;

    for (int kt = 0; kt < KT; kt++) {
        asm volatile("cp.async.wait_group %0;" :: "n"(WG) : "memory");
        __syncthreads();

        const int nf = kt + NSTG - 1;
        if (nf < KT) {
            const int sf = nf % NSTG;
            fetchA(sf, nf);
            fetchB(sf, nf);
        }
        asm volatile("cp.async.commit_group;" ::: "memory");

        const int st = kt % NSTG;
#pragma unroll
        for (int kk = 0; kk < 64; kk += 16) {
            uint32_t af[MT][4];
#pragma unroll
            for (int mt = 0; mt < MT; mt++) {
                int r0 = warpM * (BM / 2) + mt * 16 + aRowSel;
                ldsm_x4(af[mt], smem_u32(Asm + (st * BM + r0) * RSTR + kk + aColSel));
            }
            uint32_t bf[NT][2];
#pragma unroll
            for (int p = 0; p < NT / 2; p++) {
                int c0 = warpN * (BN / 4) + p * 16 + bRowSel;
                uint32_t r4[4];
                ldsm_x4(r4, smem_u32(Bsm + (st * BN + c0) * RSTR + kk + bColSel));
                bf[2 * p][0]     = r4[0];
                bf[2 * p][1]     = r4[1];
                bf[2 * p + 1][0] = r4[2];
                bf[2 * p + 1][1] = r4[3];
            }
#pragma unroll
            for (int mt = 0; mt < MT; mt++)
#pragma unroll
                for (int nt = 0; nt < NT; nt++)
                    mma_f16(acc[mt][nt], af[mt], bf[nt]);
        }
    }

    // epilogue: bias (+addin) + relu, fp16 half2 stores (ldc = N)
#pragma unroll
    for (int mt = 0; mt < MT; mt++) {
#pragma unroll
        for (int nt = 0; nt < NT; nt++) {
            int row0 = bm + warpM * (BM / 2) + mt * 16 + gp;
            int col0 = bn + warpN * (BN / 4) + nt * 8 + lq * 2;
            float b0 = bias[col0];
            float b1 = bias[col0 + 1];
            float x0 = acc[mt][nt][0] + b0;
            float x1 = acc[mt][nt][1] + b1;
            float x2 = acc[mt][nt][2] + b0;
            float x3 = acc[mt][nt][3] + b1;
            if (addin) {
                const float* p0 = addin + (size_t)row0 * N + col0;
                const float* p8 = addin + (size_t)(row0 + 8) * N + col0;
                x0 += p0[0]; x1 += p0[1];
                x2 += p8[0]; x3 += p8[1];
            }
            x0 = fmaxf(x0, 0.f); x1 = fmaxf(x1, 0.f);
            x2 = fmaxf(x2, 0.f); x3 = fmaxf(x3, 0.f);
            *(__half2*)(Cout + (size_t)row0 * N + col0) = __floats2half2_rn(x0, x1);
            *(__half2*)(Cout + (size_t)(row0 + 8) * N + col0) = __floats2half2_rn(x2, x3);
        }
    }
}

// ---------------------------------------------------------------------------
// General GEMM (off critical path): BK=32, 3-stage, AMODE/CMODE variants.
// ---------------------------------------------------------------------------
template<int BM, int BN, int AMODE, int CMODE>
__global__ __launch_bounds__(256, 2)
void gemm_f16_ldsm(const void* __restrict__ Aptr,
                   const __half* __restrict__ Wt,
                   const float* __restrict__ bias,
                   void* __restrict__ Cout,
                   int M, int N, int K, int Kp, int lda, int ldc, int flags,
                   const float* __restrict__ addin, int addld)
{
    constexpr int MT = BM / 2 / 16;
    constexpr int NT = BN / 4 / 8;

    extern __shared__ __align__(16) char smem_raw[];
    __half* Asm = (__half*)smem_raw;
    __half* Bsm = Asm + STAGES * BM * ASTR;

    const int bm   = blockIdx.y * BM;
    const int bn   = blockIdx.x * BN;
    const int tid  = threadIdx.x;
    const int lane = tid & 31;
    const int wid  = tid >> 5;
    const int warpM = wid >> 2;
    const int warpN = wid & 3;
    const int gp = lane >> 2;
    const int lq = lane & 3;

    const int KT = (K + BK - 1) / BK;

    auto fetchA = [&](int st, int kt) {
        if (AMODE == 0) {
            const __half* Ah = (const __half*)Aptr;
            constexpr int ACH = BM * 4;
#pragma unroll
            for (int i = 0; i < (ACH + 255) / 256; i++) {
                int c = i * 256 + tid;
                if (ACH >= 256 || c < ACH) {
                    int row = c >> 2;
                    int ch  = c & 3;
                    int gk0 = kt * 32 + ch * 8;
                    int rem = K - gk0;
                    int bytes = rem >= 8 ? 16 : (rem > 0 ? rem * 2 : 0);
                    const __half* g = Ah + (size_t)(bm + row) * lda + (gk0 < K ? gk0 : 0);
                    uint32_t dst = smem_u32(Asm + (st * BM + row) * ASTR + ch * 8);
                    asm volatile("cp.async.ca.shared.global [%0], [%1], 16, %2;"
                                 :: "r"(dst), "l"(g), "r"(bytes));
                }
            }
        } else {
            const __half* Sh = (const __half*)Aptr;
            constexpr int TOT = BM * 32;
#pragma unroll
            for (int i = 0; i < TOT / 256; i++) {
                int e   = i * 256 + tid;
                int row = e >> 5;
                int kc  = e & 31;
                int gk  = kt * 32 + kc;
                int gr  = bm + row;
                int tt  = gr >> 10;
                int b   = gr & 1023;
                __half v = __float2half(0.f);
                if (gk < 72) v = Sh[(size_t)b * 3072 + tt * 36 + gk];
                Asm[(st * BM + row) * ASTR + kc] = v;
            }
        }
    };

    auto fetchB = [&](int st, int kt) {
        constexpr int BCH = BN * 4;
#pragma unroll
        for (int i = 0; i < (BCH + 255) / 256; i++) {
            int c = i * 256 + tid;
            if (BCH >= 256 || c < BCH) {
                int row = c >> 2;
                int ch  = c & 3;
                int gn  = bn + row;
                int bytes = (gn < N) ? 16 : 0;
                const __half* g = Wt + (size_t)(gn < N ? gn : 0) * Kp + kt * 32 + ch * 8;
                uint32_t dst = smem_u32(Bsm + (st * BN + row) * ASTR + ch * 8);
                asm volatile("cp.async.ca.shared.global [%0], [%1], 16, %2;"
                             :: "r"(dst), "l"(g), "r"(bytes));
            }
        }
    };

    float acc[MT][NT][4];
#pragma unroll
    for (int i = 0; i < MT; i++)
#pragma unroll
        for (int j = 0; j < NT; j++)
#pragma unroll
            for (int v = 0; v < 4; v++) acc[i][j][v] = 0.f;

#pragma unroll
    for (int s = 0; s < STAGES - 1; s++) {
        if (s < KT) { fetchA(s, s); fetchB(s, s); }
        asm volatile("cp.async.commit_group;" ::: "memory");
    }

    const int aRowSel = lane & 15;
    const int aColSel = (lane >> 4) << 3;
    const int bRowSel = ((lane >> 4) << 3) + (lane & 7);
    const int bColSel = ((lane >> 3) & 1) << 3;

    for (int kt = 0; kt < KT; kt++) {
        asm volatile("cp.async.wait_group 1;" ::: "memory");
        __syncthreads();

        const int nf = kt + 2;
        if (nf < KT) { fetchA(nf % STAGES, nf); fetchB(nf % STAGES, nf); }
        asm volatile("cp.async.commit_group;" ::: "memory");

        const int st = kt % STAGES;
#pragma unroll
        for (int kk = 0; kk < BK; kk += 16) {
            uint32_t af[MT][4];
#pragma unroll
            for (int mt = 0; mt < MT; mt++) {
                int r0 = warpM * (BM / 2) + mt * 16 + aRowSel;
                ldsm_x4(af[mt], smem_u32(Asm + (st * BM + r0) * ASTR + kk + aColSel));
            }
            uint32_t bf[NT][2];
#pragma unroll
            for (int p = 0; p < NT / 2; p++) {
                int c0 = warpN * (BN / 4) + p * 16 + bRowSel;
                uint32_t r4[4];
                ldsm_x4(r4, smem_u32(Bsm + (st * BN + c0) * ASTR + kk + bColSel));
                bf[2 * p][0]     = r4[0];
                bf[2 * p][1]     = r4[1];
                bf[2 * p + 1][0] = r4[2];
                bf[2 * p + 1][1] = r4[3];
            }
#pragma unroll
            for (int mt = 0; mt < MT; mt++)
#pragma unroll
                for (int nt = 0; nt < NT; nt++)
                    mma_f16(acc[mt][nt], af[mt], bf[nt]);
        }
    }

    const bool relu = flags & 1;
    const bool houT = flags & 2;
    const bool padd = flags & 4;
#pragma unroll
    for (int mt = 0; mt < MT; mt++) {
#pragma unroll
        for (int nt = 0; nt < NT; nt++) {
            int row0 = bm + warpM * (BM / 2) + mt * 16 + gp;
            int col0 = bn + warpN * (BN / 4) + nt * 8 + lq * 2;
            float b0 = (col0 < N)     ? bias[col0]     : 0.f;
            float b1 = (col0 + 1 < N) ? bias[col0 + 1] : 0.f;
            float x0 = acc[mt][nt][0] + b0;
            float x1 = acc[mt][nt][1] + b1;
            float x2 = acc[mt][nt][2] + b0;
            float x3 = acc[mt][nt][3] + b1;
            if (padd) {
                const float* p0 = addin + (size_t)row0 * addld + col0;
                const float* p8 = addin + (size_t)(row0 + 8) * addld + col0;
                x0 += p0[0]; x1 += p0[1];
                x2 += p8[0]; x3 += p8[1];
            }
            if (relu) {
                x0 = fmaxf(x0, 0.f); x1 = fmaxf(x1, 0.f);
                x2 = fmaxf(x2, 0.f); x3 = fmaxf(x3, 0.f);
            }
            if (CMODE == 1) {
                float* cp = (float*)Cout;
                int ta = (row0 >> 10) + 1,  ba = row0 & 1023;
                int tb = ((row0 + 8) >> 10) + 1, bbx = (row0 + 8) & 1023;
                size_t oa = (size_t)ba * ldc + (size_t)ta * C_;
                size_t ob = (size_t)bbx * ldc + (size_t)tb * C_;
                if (col0 < N)     { cp[oa + col0] = x0;     cp[ob + col0] = x2; }
                if (col0 + 1 < N) { cp[oa + col0 + 1] = x1; cp[ob + col0 + 1] = x3; }
            } else if (houT) {
                __half* cp = (__half*)Cout;
                *(__half2*)(cp + (size_t)row0 * ldc + col0) = __floats2half2_rn(x0, x1);
                *(__half2*)(cp + (size_t)(row0 + 8) * ldc + col0) = __floats2half2_rn(x2, x3);
            } else {
                float* cp = (float*)Cout;
                if (col0 < N) {
                    cp[(size_t)row0 * ldc + col0] = x0;
                    cp[(size_t)(row0 + 8) * ldc + col0] = x2;
                }
                if (col0 + 1 < N) {
                    cp[(size_t)row0 * ldc + col0 + 1] = x1;
                    cp[(size_t)(row0 + 8) * ldc + col0 + 1] = x3;
                }
            }
        }
    }
}

// ---------------------------------------------------------------------------
// Prep kernels
// ---------------------------------------------------------------------------
__global__ void src_round_kernel(const float* __restrict__ src,
                                 __half* __restrict__ dst)
{
    int i = blockIdx.x * blockDim.x + threadIdx.x;
    if (i >= B_ * 3072) return;
    int b = i / 3072;
    int j = i - b * 3072;
    float v = (j < T_ * F_) ? src[(size_t)b * T_ * F_ + j] : 0.f;
    dst[i] = __float2half(v);
}

__global__ void transpose_h_kernel(const float* __restrict__ W,
                                   __half* __restrict__ Wt,
                                   int K, int N, int Kp, int ldw)
{
    __shared__ float tile[32][33];
    int k0 = blockIdx.x * 32;
    int n0 = blockIdx.y * 32;
    int tx = threadIdx.x, ty = threadIdx.y;
    for (int i = ty; i < 32; i += 8) {
        int k = k0 + i, n = n0 + tx;
        tile[i][tx] = (k < K && n < N) ? W[(size_t)k * ldw + n] : 0.f;
    }
    __syncthreads();
    for (int i = ty; i < 32; i += 8) {
        int n = n0 + i, k = k0 + tx;
        if (n < N && k < Kp)
            Wt[(size_t)n * Kp + k] = __float2half(tile[tx][i]);
    }
}

__global__ void compose_w_kernel(const float* __restrict__ W1,
                                 const float* __restrict__ W2,
                                 __half* __restrict__ outT,
                                 int D, int I, int N)
{
    __shared__ float row[512];
    int d = blockIdx.x;
    for (int i = threadIdx.x; i < I; i += 128) row[i] = W1[(size_t)d * I + i];
    __syncthreads();
    for (int n = threadIdx.x; n < N; n += 128) {
        float s = 0.f;
        for (int i = 0; i < I; i++) s += row[i] * W2[(size_t)i * N + n];
        outT[(size_t)n * D + d] = __float2half(s);
    }
}

__global__ void compose_w_f32_kernel(const float* __restrict__ W1,
                                     const float* __restrict__ W2,
                                     float* __restrict__ outp,
                                     int D, int I, int N)
{
    __shared__ float row[512];
    int d = blockIdx.x;
    for (int i = threadIdx.x; i < I; i += 128) row[i] = W1[(size_t)d * I + i];
    __syncthreads();
    for (int n = threadIdx.x; n < N; n += 128) {
        float s = 0.f;
        for (int i = 0; i < I; i++) s += row[i] * W2[(size_t)i * N + n];
        outp[(size_t)d * N + n] = s;
    }
}

__global__ void compose_bias_kernel(const float* __restrict__ b1,
                                    const float* __restrict__ W2,
                                    const float* __restrict__ b2,
                                    float* __restrict__ bc, int I, int N)
{
    int n = threadIdx.x;
    if (n >= N) return;
    float s = b2[n];
    for (int i = 0; i < I; i++) s += b1[i] * W2[(size_t)i * N + n];
    bc[n] = s;
}

__global__ void compose_bias_wide_kernel(const float* __restrict__ bsrc,
                                         const float* __restrict__ W,
                                         float* __restrict__ outp,
                                         int I, int N, int ldw)
{
    int n = blockIdx.x * blockDim.x + threadIdx.x;
    if (n >= N) return;
    float s = 0.f;
    for (int i = 0; i < I; i++) s += bsrc[i] * W[(size_t)i * ldw + n];
    outp[n] = s;
}

__global__ void copy_init_tail_kernel(float* __restrict__ out)
{
    int i = blockIdx.x * blockDim.x + threadIdx.x;
    if (i >= B_ * C_) return;
    int b = i / C_;
    int c = i - b * C_;
    out[(size_t)B_ * T_ * C_ + i] = out[(size_t)b * T_ * C_ + c];
}

// ---------------------------------------------------------------------------
template<int BM, int BN, int AMODE, int CMODE>
static void launch_gemm(const void* A, const __half* Wt, const float* bias,
                        void* C, int M, int N, int K, int Kp, int lda, int ldc,
                        int flags, const float* addin = nullptr, int addld = 0)
{
    const int sbytes = STAGES * (BM + BN) * ASTR * 2;
    cudaFuncSetAttribute(gemm_f16_ldsm<BM, BN, AMODE, CMODE>,
                         cudaFuncAttributeMaxDynamicSharedMemorySize, sbytes);
    dim3 grid((N + BN - 1) / BN, M / BM);
    gemm_f16_ldsm<BM, BN, AMODE, CMODE><<<grid, 256, sbytes>>>(
        A, Wt, bias, C, M, N, K, Kp, lda, ldc, flags, addin, addld);
}

template<int BM, int BN, int NSTG>
static void launch_scan(const __half* A, const __half* Wt, const float* bias,
                        __half* C, int N, int K, const float* addin = nullptr)
{
    const int sbytes = NSTG * (BM + BN) * 72 * 2;
    cudaFuncSetAttribute(scan_gemm<BM, BN, NSTG>,
                         cudaFuncAttributeMaxDynamicSharedMemorySize, sbytes);
    dim3 grid(N / BN, 1024 / BM);
    scan_gemm<BM, BN, NSTG><<<grid, 256, sbytes>>>(A, Wt, bias, C, N, K, addin);
}

static void trsp(const float* W, __half* Wt, int K, int N, int Kp, int ldw)
{
    dim3 grid((Kp + 31) / 32, (N + 31) / 32);
    transpose_h_kernel<<<grid, dim3(32, 8)>>>(W, Wt, K, N, Kp, ldw);
}

extern "C" void kernel_launch(void* const* d_in, const int* in_sizes, int n_in,
                              void* d_out, int out_size)
{
    const float* src  = (const float*)d_in[0];
    const float* wi1  = (const float*)d_in[1];
    const float* bi1  = (const float*)d_in[2];
    const float* wi2  = (const float*)d_in[3];
    const float* bi2  = (const float*)d_in[4];
    const float* wi25 = (const float*)d_in[5];
    const float* bi25 = (const float*)d_in[6];
    const float* wi3  = (const float*)d_in[7];
    const float* bi3  = (const float*)d_in[8];
    const float* w1   = (const float*)d_in[9];
    const float* b1   = (const float*)d_in[10];
    const float* w12  = (const float*)d_in[11];
    const float* b12  = (const float*)d_in[12];
    const float* w2   = (const float*)d_in[13];
    const float* b2   = (const float*)d_in[14];
    const float* w22  = (const float*)d_in[15];
    const float* b22  = (const float*)d_in[16];
    const float* w3   = (const float*)d_in[17];
    const float* b3   = (const float*)d_in[18];
    const float* w4   = (const float*)d_in[19];
    const float* b4   = (const float*)d_in[20];
    const float* w4d  = (const float*)d_in[21];
    const float* b4d  = (const float*)d_in[22];

    float* out = (float*)d_out;

    __half *hA, *hB, *hC, *S, *srch, *wh;
    float *bc, *bb, *bbi, *w4c32, *P;
    cudaGetSymbolAddress((void**)&hA,    g_hA);
    cudaGetSymbolAddress((void**)&hB,    g_hB);
    cudaGetSymbolAddress((void**)&hC,    g_hC);
    cudaGetSymbolAddress((void**)&S,     g_S);
    cudaGetSymbolAddress((void**)&srch,  g_srch);
    cudaGetSymbolAddress((void**)&wh,    g_wh);
    cudaGetSymbolAddress((void**)&bc,    g_bc);
    cudaGetSymbolAddress((void**)&bb,    g_bb);
    cudaGetSymbolAddress((void**)&bbi,   g_bbi);
    cudaGetSymbolAddress((void**)&w4c32, g_w4c32);
    cudaGetSymbolAddress((void**)&P,     g_P);

    const float* W1c = w1 + 72 * 2048;   // rows 72..140 of w1

    // ---- prep ----
    trsp(wi1,  wh + OFF_WI1T,  3060, 2048, 3072, 2048);
    trsp(wi2,  wh + OFF_WI2T,  2048, 1024, 2048, 1024);
    trsp(wi25, wh + OFF_WI25T, 1024, 512,  1024, 512);
    trsp(wi3,  wh + OFF_WI3T,  512,  69,   512,  69);
    trsp(w1,   wh + OFF_W1ABT, 72,   2048, 96,   2048);
    trsp(w12,  wh + OFF_W12T,  2048, 2048, 2048, 2048);
    trsp(w2,   wh + OFF_W2T,   2048, 1024, 2048, 1024);
    trsp(w22,  wh + OFF_W22T,  1024, 1024, 1024, 1024);
    trsp(w3,   wh + OFF_W3T,   1024, 512,  1024, 512);

    compose_w_f32_kernel<<<512, 128>>>(w4, w4d, w4c32, 512, 512, C_);
    trsp(w4c32, wh + OFF_W4CT, 512, C_, 512, C_);
    compose_w_kernel<<<512, 128>>>(w4c32, W1c, wh + OFF_W41T,  512, C_, 2048);
    compose_w_kernel<<<512, 128>>>(wi3,   W1c, wh + OFF_WI31T, 512, C_, 2048);
    compose_bias_kernel<<<1, 128>>>(b4, w4d, b4d, bc, 512, C_);
    compose_bias_wide_kernel<<<8, 256>>>(bc,  W1c, bb,  C_, 2048, 2048);
    compose_bias_wide_kernel<<<8, 256>>>(bi3, W1c, bbi, C_, 2048, 2048);
    src_round_kernel<<<(B_ * 3072 + 511) / 512, 512>>>(src, srch);

    const int LDO = T_ * C_;

    // ---- P = concat(src[t-1],src[t]) @ W1ab + b1, all 84 steps at once
    launch_gemm<64, 128, 2, 0>(srch, wh + OFF_W1ABT, b1, P,
                               (T_ - 1) * B_, 2048, 72, 96, 0, 2048, 0);

    // ---- init MLP: 3060 -> 2048 -> 1024 -> h25(512) -> out[:,0,:]
    launch_gemm<64, 128, 0, 0>(srch, wh + OFF_WI1T, bi1, hA,
                               B_, 2048, 3060, 3072, 3072, 2048, 3);
    launch_gemm<64, 64, 0, 0>(hA, wh + OFF_WI2T, bi2, hB,
                              B_, 1024, 2048, 2048, 2048, 1024, 3);
    launch_gemm<32, 64, 0, 0>(hB, wh + OFF_WI25T, bi25, hC,
                              B_, 512, 1024, 1024, 1024, 512, 2);
    launch_gemm<64, 128, 0, 0>(hC, wh + OFF_WI3T, bi3, out,
                               B_, C_, 512, 512, 512, LDO, 0);

    // ---- scan: 84 steps x 5 GEMMs (R9 core; L12 retiled to 128x64, 256 blk)
    for (int t = 1; t < T_; t++) {
        const __half* sPrev = (t == 1) ? hC : S + (size_t)(t - 2) * B_ * H_;
        const __half* Wl1   = (t == 1) ? (wh + OFF_WI31T) : (wh + OFF_W41T);
        const float*  bl1   = (t == 1) ? bbi : bb;

        launch_scan< 64, 128, 3>(sPrev, Wl1, bl1, hA, 2048, 512,
                                 P + (size_t)(t - 1) * B_ * 2048);
        launch_scan<128,  64, 3>(hA, wh + OFF_W12T, b12, hB, 2048, 2048);
        launch_scan< 64, 128, 3>(hB, wh + OFF_W2T,  b2,  hA, 1024, 2048);
        launch_scan< 64, 128, 3>(hA, wh + OFF_W22T, b22, hB, 1024, 1024);
        launch_scan< 64,  64, 3>(hB, wh + OFF_W3T,  b3,
                                 S + (size_t)(t - 1) * B_ * H_, 512, 1024);
    }

    // ---- all out[:,t,:] (t=1..84) in one batched scatter GEMM
    launch_gemm<64, 128, 0, 1>(S, wh + OFF_W4CT, bc, out,
                               (T_ - 1) * B_, C_, 512, 512, 512, LDO, 0);

    if (out_size >= B_ * T_ * C_ + B_ * C_) {
        copy_init_tail_kernel<<<(B_ * C_ + 255) / 256, 256>>>(out);
    }
}

// round 13
// speedup vs baseline: 1.0977x; 1.0977x over previous
#include <cuda_runtime.h>
#include <cuda_fp16.h>
#include <cstdint>
#include <cstddef>

// Problem constants
#define B_  1024
#define T_  85
#define F_  36
#define H_  512
#define C_  69

#define ASTR 40        // general kernel: halfs per smem row (32 data + 8 pad)
#define BK 32
#define STAGES 3

// ---------------------------------------------------------------------------
// Device globals
// ---------------------------------------------------------------------------
__device__ __half g_hA[B_ * 4 * H_];
__device__ __half g_hB[B_ * 4 * H_];
__device__ __half g_hC[B_ * H_];                        // h25 (init 512-wide)
__device__ __half g_S[(size_t)(T_ - 1) * B_ * H_];      // all s_t (fp16)
__device__ __half g_srch[B_ * 3072];
__device__ float  g_bc[C_];                             // composed out bias
__device__ float  g_bb[2048];                           // bc @ W1c
__device__ float  g_bbi[2048];                          // bi3 @ W1c
__device__ float  g_w4c32[H_ * C_];                     // w4@w4d fp32
__device__ float  g_P[(size_t)(T_ - 1) * B_ * 2048];    // layer-1 partial (incl b1)

// fp16 K-major weights [N][Kp], packed (offsets in halfs)
#define OFF_WI1T    0u          /* 2048 x 3072 */
#define OFF_WI2T    6291456u    /* 1024 x 2048 */
#define OFF_WI25T   8388608u    /* 512  x 1024 */
#define OFF_WI3T    8912896u    /* 69   x 512  */
#define OFF_W1ABT   8948224u    /* 2048 x 96   */
#define OFF_W12T    9144832u    /* 2048 x 2048 */
#define OFF_W2T     13339136u   /* 1024 x 2048 */
#define OFF_W22T    15436288u   /* 1024 x 1024 */
#define OFF_W3T     16484864u   /* 512  x 1024 */
#define OFF_W4CT    17009152u   /* 69   x 512  */
#define OFF_W41T    17044480u   /* 2048 x 512  */
#define OFF_WI31T   18093056u   /* 2048 x 512  */
#define WH_TOTAL    19141632u
__device__ __half g_wh[WH_TOTAL];

// ---------------------------------------------------------------------------
__device__ __forceinline__ uint32_t smem_u32(const void* p) {
    return (uint32_t)__cvta_generic_to_shared(p);
}

__device__ __forceinline__ void mma_f16(float (&d)[4],
                                        const uint32_t (&a)[4],
                                        const uint32_t (&b)[2]) {
    asm volatile(
        "mma.sync.aligned.m16n8k16.row.col.f32.f16.f16.f32 "
        "{%0,%1,%2,%3}, {%4,%5,%6,%7}, {%8,%9}, {%0,%1,%2,%3};"
        : "+f"(d[0]), "+f"(d[1]), "+f"(d[2]), "+f"(d[3])
        : "r"(a[0]), "r"(a[1]), "r"(a[2]), "r"(a[3]),
          "r"(b[0]), "r"(b[1]));
}

__device__ __forceinline__ void ldsm_x4(uint32_t (&r)[4], uint32_t addr) {
    asm volatile(
        "ldmatrix.sync.aligned.m8n8.x4.shared.b16 {%0,%1,%2,%3}, [%4];"
        : "=r"(r[0]), "=r"(r[1]), "=r"(r[2]), "=r"(r[3]) : "r"(addr));
}

// ---------------------------------------------------------------------------
// Scan-layer GEMM (fast path, R9 core): M = 1024 fixed, exact tiling, BK=64.
// C[1024,N] = relu(A[1024,K] @ Wt[N,K]^T + bias [+ addin]), fp16 out, ldc=N.
// ---------------------------------------------------------------------------
template<int BM, int BN, int NSTG>
__global__ __launch_bounds__(256, 2)
void scan_gemm(const __half* __restrict__ A,
               const __half* __restrict__ Wt,
               const float* __restrict__ bias,
               __half* __restrict__ Cout,
               int N, int K,
               const float* __restrict__ addin)
{
    constexpr int RSTR = 72;       // 64 data + 8 pad halfs
    constexpr int MT = BM / 32;
    constexpr int NT = BN / 32;
    constexpr int WG = NSTG - 2;   // wait_group depth

    extern __shared__ __align__(16) char smem_raw[];
    __half* Asm = (__half*)smem_raw;
    __half* Bsm = Asm + NSTG * BM * RSTR;

    const int bm   = blockIdx.y * BM;
    const int bn   = blockIdx.x * BN;
    const int tid  = threadIdx.x;
    const int lane = tid & 31;
    const int wid  = tid >> 5;
    const int warpM = wid >> 2;
    const int warpN = wid & 3;
    const int gp = lane >> 2;
    const int lq = lane & 3;

    const int KT = K >> 6;         // K / 64

    auto fetchA = [&](int st, int kt) {
#pragma unroll
        for (int i = 0; i < BM / 32; i++) {
            int c   = i * 256 + tid;
            int row = c >> 3;
            int ch  = c & 7;
            const __half* g = A + (size_t)(bm + row) * K + kt * 64 + ch * 8;
            uint32_t dst = smem_u32(Asm + (st * BM + row) * RSTR + ch * 8);
            asm volatile("cp.async.ca.shared.global [%0], [%1], 16;"
                         :: "r"(dst), "l"(g));
        }
    };
    auto fetchB = [&](int st, int kt) {
#pragma unroll
        for (int i = 0; i < BN / 32; i++) {
            int c   = i * 256 + tid;
            int row = c >> 3;
            int ch  = c & 7;
            const __half* g = Wt + (size_t)(bn + row) * K + kt * 64 + ch * 8;
            uint32_t dst = smem_u32(Bsm + (st * BN + row) * RSTR + ch * 8);
            asm volatile("cp.async.ca.shared.global [%0], [%1], 16;"
                         :: "r"(dst), "l"(g));
        }
    };

    float acc[MT][NT][4];
#pragma unroll
    for (int i = 0; i < MT; i++)
#pragma unroll
        for (int j = 0; j < NT; j++)
#pragma unroll
            for (int v = 0; v < 4; v++) acc[i][j][v] = 0.f;

#pragma unroll
    for (int s = 0; s < NSTG - 1; s++) {
        if (s < KT) { fetchA(s, s); fetchB(s, s); }
        asm volatile("cp.async.commit_group;" ::: "memory");
    }

    const int aRowSel = lane & 15;
    const int aColSel = (lane >> 4) << 3;
    const int bRowSel = ((lane >> 4) << 3) + (lane & 7);
    const int bColSel = ((lane >> 3) & 1) << 3;

    for (int kt = 0; kt < KT; kt++) {
        asm volatile("cp.async.wait_group %0;" :: "n"(WG) : "memory");
        __syncthreads();

        const int nf = kt + NSTG - 1;
        if (nf < KT) {
            const int sf = nf % NSTG;
            fetchA(sf, nf);
            fetchB(sf, nf);
        }
        asm volatile("cp.async.commit_group;" ::: "memory");

        const int st = kt % NSTG;
#pragma unroll
        for (int kk = 0; kk < 64; kk += 16) {
            uint32_t af[MT][4];
#pragma unroll
            for (int mt = 0; mt < MT; mt++) {
                int r0 = warpM * (BM / 2) + mt * 16 + aRowSel;
                ldsm_x4(af[mt], smem_u32(Asm + (st * BM + r0) * RSTR + kk + aColSel));
            }
            uint32_t bf[NT][2];
#pragma unroll
            for (int p = 0; p < NT / 2; p++) {
                int c0 = warpN * (BN / 4) + p * 16 + bRowSel;
                uint32_t r4[4];
                ldsm_x4(r4, smem_u32(Bsm + (st * BN + c0) * RSTR + kk + bColSel));
                bf[2 * p][0]     = r4[0];
                bf[2 * p][1]     = r4[1];
                bf[2 * p + 1][0] = r4[2];
                bf[2 * p + 1][1] = r4[3];
            }
#pragma unroll
            for (int mt = 0; mt < MT; mt++)
#pragma unroll
                for (int nt = 0; nt < NT; nt++)
                    mma_f16(acc[mt][nt], af[mt], bf[nt]);
        }
    }

    // epilogue: bias (+addin) + relu, fp16 half2 stores (ldc = N)
#pragma unroll
    for (int mt = 0; mt < MT; mt++) {
#pragma unroll
        for (int nt = 0; nt < NT; nt++) {
            int row0 = bm + warpM * (BM / 2) + mt * 16 + gp;
            int col0 = bn + warpN * (BN / 4) + nt * 8 + lq * 2;
            float b0 = bias[col0];
            float b1 = bias[col0 + 1];
            float x0 = acc[mt][nt][0] + b0;
            float x1 = acc[mt][nt][1] + b1;
            float x2 = acc[mt][nt][2] + b0;
            float x3 = acc[mt][nt][3] + b1;
            if (addin) {
                const float* p0 = addin + (size_t)row0 * N + col0;
                const float* p8 = addin + (size_t)(row0 + 8) * N + col0;
                x0 += p0[0]; x1 += p0[1];
                x2 += p8[0]; x3 += p8[1];
            }
            x0 = fmaxf(x0, 0.f); x1 = fmaxf(x1, 0.f);
            x2 = fmaxf(x2, 0.f); x3 = fmaxf(x3, 0.f);
            *(__half2*)(Cout + (size_t)row0 * N + col0) = __floats2half2_rn(x0, x1);
            *(__half2*)(Cout + (size_t)(row0 + 8) * N + col0) = __floats2half2_rn(x2, x3);
        }
    }
}

// ---------------------------------------------------------------------------
// General GEMM (off critical path): BK=32, 3-stage, AMODE/CMODE variants.
// ---------------------------------------------------------------------------
template<int BM, int BN, int AMODE, int CMODE>
__global__ __launch_bounds__(256, 2)
void gemm_f16_ldsm(const void* __restrict__ Aptr,
                   const __half* __restrict__ Wt,
                   const float* __restrict__ bias,
                   void* __restrict__ Cout,
                   int M, int N, int K, int Kp, int lda, int ldc, int flags,
                   const float* __restrict__ addin, int addld)
{
    constexpr int MT = BM / 2 / 16;
    constexpr int NT = BN / 4 / 8;

    extern __shared__ __align__(16) char smem_raw[];
    __half* Asm = (__half*)smem_raw;
    __half* Bsm = Asm + STAGES * BM * ASTR;

    const int bm   = blockIdx.y * BM;
    const int bn   = blockIdx.x * BN;
    const int tid  = threadIdx.x;
    const int lane = tid & 31;
    const int wid  = tid >> 5;
    const int warpM = wid >> 2;
    const int warpN = wid & 3;
    const int gp = lane >> 2;
    const int lq = lane & 3;

    const int KT = (K + BK - 1) / BK;

    auto fetchA = [&](int st, int kt) {
        if (AMODE == 0) {
            const __half* Ah = (const __half*)Aptr;
            constexpr int ACH = BM * 4;
#pragma unroll
            for (int i = 0; i < (ACH + 255) / 256; i++) {
                int c = i * 256 + tid;
                if (ACH >= 256 || c < ACH) {
                    int row = c >> 2;
                    int ch  = c & 3;
                    int gk0 = kt * 32 + ch * 8;
                    int rem = K - gk0;
                    int bytes = rem >= 8 ? 16 : (rem > 0 ? rem * 2 : 0);
                    const __half* g = Ah + (size_t)(bm + row) * lda + (gk0 < K ? gk0 : 0);
                    uint32_t dst = smem_u32(Asm + (st * BM + row) * ASTR + ch * 8);
                    asm volatile("cp.async.ca.shared.global [%0], [%1], 16, %2;"
                                 :: "r"(dst), "l"(g), "r"(bytes));
                }
            }
        } else {
            const __half* Sh = (const __half*)Aptr;
            constexpr int TOT = BM * 32;
#pragma unroll
            for (int i = 0; i < TOT / 256; i++) {
                int e   = i * 256 + tid;
                int row = e >> 5;
                int kc  = e & 31;
                int gk  = kt * 32 + kc;
                int gr  = bm + row;
                int tt  = gr >> 10;
                int b   = gr & 1023;
                __half v = __float2half(0.f);
                if (gk < 72) v = Sh[(size_t)b * 3072 + tt * 36 + gk];
                Asm[(st * BM + row) * ASTR + kc] = v;
            }
        }
    };

    auto fetchB = [&](int st, int kt) {
        constexpr int BCH = BN * 4;
#pragma unroll
        for (int i = 0; i < (BCH + 255) / 256; i++) {
            int c = i * 256 + tid;
            if (BCH >= 256 || c < BCH) {
                int row = c >> 2;
                int ch  = c & 3;
                int gn  = bn + row;
                int bytes = (gn < N) ? 16 : 0;
                const __half* g = Wt + (size_t)(gn < N ? gn : 0) * Kp + kt * 32 + ch * 8;
                uint32_t dst = smem_u32(Bsm + (st * BN + row) * ASTR + ch * 8);
                asm volatile("cp.async.ca.shared.global [%0], [%1], 16, %2;"
                             :: "r"(dst), "l"(g), "r"(bytes));
            }
        }
    };

    float acc[MT][NT][4];
#pragma unroll
    for (int i = 0; i < MT; i++)
#pragma unroll
        for (int j = 0; j < NT; j++)
#pragma unroll
            for (int v = 0; v < 4; v++) acc[i][j][v] = 0.f;

#pragma unroll
    for (int s = 0; s < STAGES - 1; s++) {
        if (s < KT) { fetchA(s, s); fetchB(s, s); }
        asm volatile("cp.async.commit_group;" ::: "memory");
    }

    const int aRowSel = lane & 15;
    const int aColSel = (lane >> 4) << 3;
    const int bRowSel = ((lane >> 4) << 3) + (lane & 7);
    const int bColSel = ((lane >> 3) & 1) << 3;

    for (int kt = 0; kt < KT; kt++) {
        asm volatile("cp.async.wait_group 1;" ::: "memory");
        __syncthreads();

        const int nf = kt + 2;
        if (nf < KT) { fetchA(nf % STAGES, nf); fetchB(nf % STAGES, nf); }
        asm volatile("cp.async.commit_group;" ::: "memory");

        const int st = kt % STAGES;
#pragma unroll
        for (int kk = 0; kk < BK; kk += 16) {
            uint32_t af[MT][4];
#pragma unroll
            for (int mt = 0; mt < MT; mt++) {
                int r0 = warpM * (BM / 2) + mt * 16 + aRowSel;
                ldsm_x4(af[mt], smem_u32(Asm + (st * BM + r0) * ASTR + kk + aColSel));
            }
            uint32_t bf[NT][2];
#pragma unroll
            for (int p = 0; p < NT / 2; p++) {
                int c0 = warpN * (BN / 4) + p * 16 + bRowSel;
                uint32_t r4[4];
                ldsm_x4(r4, smem_u32(Bsm + (st * BN + c0) * ASTR + kk + bColSel));
                bf[2 * p][0]     = r4[0];
                bf[2 * p][1]     = r4[1];
                bf[2 * p + 1][0] = r4[2];
                bf[2 * p + 1][1] = r4[3];
            }
#pragma unroll
            for (int mt = 0; mt < MT; mt++)
#pragma unroll
                for (int nt = 0; nt < NT; nt++)
                    mma_f16(acc[mt][nt], af[mt], bf[nt]);
        }
    }

    const bool relu = flags & 1;
    const bool houT = flags & 2;
    const bool padd = flags & 4;
#pragma unroll
    for (int mt = 0; mt < MT; mt++) {
#pragma unroll
        for (int nt = 0; nt < NT; nt++) {
            int row0 = bm + warpM * (BM / 2) + mt * 16 + gp;
            int col0 = bn + warpN * (BN / 4) + nt * 8 + lq * 2;
            float b0 = (col0 < N)     ? bias[col0]     : 0.f;
            float b1 = (col0 + 1 < N) ? bias[col0 + 1] : 0.f;
            float x0 = acc[mt][nt][0] + b0;
            float x1 = acc[mt][nt][1] + b1;
            float x2 = acc[mt][nt][2] + b0;
            float x3 = acc[mt][nt][3] + b1;
            if (padd) {
                const float* p0 = addin + (size_t)row0 * addld + col0;
                const float* p8 = addin + (size_t)(row0 + 8) * addld + col0;
                x0 += p0[0]; x1 += p0[1];
                x2 += p8[0]; x3 += p8[1];
            }
            if (relu) {
                x0 = fmaxf(x0, 0.f); x1 = fmaxf(x1, 0.f);
                x2 = fmaxf(x2, 0.f); x3 = fmaxf(x3, 0.f);
            }
            if (CMODE == 1) {
                float* cp = (float*)Cout;
                int ta = (row0 >> 10) + 1,  ba = row0 & 1023;
                int tb = ((row0 + 8) >> 10) + 1, bbx = (row0 + 8) & 1023;
                size_t oa = (size_t)ba * ldc + (size_t)ta * C_;
                size_t ob = (size_t)bbx * ldc + (size_t)tb * C_;
                if (col0 < N)     { cp[oa + col0] = x0;     cp[ob + col0] = x2; }
                if (col0 + 1 < N) { cp[oa + col0 + 1] = x1; cp[ob + col0 + 1] = x3; }
            } else if (houT) {
                __half* cp = (__half*)Cout;
                *(__half2*)(cp + (size_t)row0 * ldc + col0) = __floats2half2_rn(x0, x1);
                *(__half2*)(cp + (size_t)(row0 + 8) * ldc + col0) = __floats2half2_rn(x2, x3);
            } else {
                float* cp = (float*)Cout;
                if (col0 < N) {
                    cp[(size_t)row0 * ldc + col0] = x0;
                    cp[(size_t)(row0 + 8) * ldc + col0] = x2;
                }
                if (col0 + 1 < N) {
                    cp[(size_t)row0 * ldc + col0 + 1] = x1;
                    cp[(size_t)(row0 + 8) * ldc + col0 + 1] = x3;
                }
            }
        }
    }
}

// ---------------------------------------------------------------------------
// Prep kernels
// ---------------------------------------------------------------------------
__global__ void src_round_kernel(const float* __restrict__ src,
                                 __half* __restrict__ dst)
{
    int i = blockIdx.x * blockDim.x + threadIdx.x;
    if (i >= B_ * 3072) return;
    int b = i / 3072;
    int j = i - b * 3072;
    float v = (j < T_ * F_) ? src[(size_t)b * T_ * F_ + j] : 0.f;
    dst[i] = __float2half(v);
}

__global__ void transpose_h_kernel(const float* __restrict__ W,
                                   __half* __restrict__ Wt,
                                   int K, int N, int Kp, int ldw)
{
    __shared__ float tile[32][33];
    int k0 = blockIdx.x * 32;
    int n0 = blockIdx.y * 32;
    int tx = threadIdx.x, ty = threadIdx.y;
    for (int i = ty; i < 32; i += 8) {
        int k = k0 + i, n = n0 + tx;
        tile[i][tx] = (k < K && n < N) ? W[(size_t)k * ldw + n] : 0.f;
    }
    __syncthreads();
    for (int i = ty; i < 32; i += 8) {
        int n = n0 + i, k = k0 + tx;
        if (n < N && k < Kp)
            Wt[(size_t)n * Kp + k] = __float2half(tile[tx][i]);
    }
}

__global__ void compose_w_kernel(const float* __restrict__ W1,
                                 const float* __restrict__ W2,
                                 __half* __restrict__ outT,
                                 int D, int I, int N)
{
    __shared__ float row[512];
    int d = blockIdx.x;
    for (int i = threadIdx.x; i < I; i += 128) row[i] = W1[(size_t)d * I + i];
    __syncthreads();
    for (int n = threadIdx.x; n < N; n += 128) {
        float s = 0.f;
        for (int i = 0; i < I; i++) s += row[i] * W2[(size_t)i * N + n];
        outT[(size_t)n * D + d] = __float2half(s);
    }
}

__global__ void compose_w_f32_kernel(const float* __restrict__ W1,
                                     const float* __restrict__ W2,
                                     float* __restrict__ outp,
                                     int D, int I, int N)
{
    __shared__ float row[512];
    int d = blockIdx.x;
    for (int i = threadIdx.x; i < I; i += 128) row[i] = W1[(size_t)d * I + i];
    __syncthreads();
    for (int n = threadIdx.x; n < N; n += 128) {
        float s = 0.f;
        for (int i = 0; i < I; i++) s += row[i] * W2[(size_t)i * N + n];
        outp[(size_t)d * N + n] = s;
    }
}

__global__ void compose_bias_kernel(const float* __restrict__ b1,
                                    const float* __restrict__ W2,
                                    const float* __restrict__ b2,
                                    float* __restrict__ bc, int I, int N)
{
    int n = threadIdx.x;
    if (n >= N) return;
    float s = b2[n];
    for (int i = 0; i < I; i++) s += b1[i] * W2[(size_t)i * N + n];
    bc[n] = s;
}

__global__ void compose_bias_wide_kernel(const float* __restrict__ bsrc,
                                         const float* __restrict__ W,
                                         float* __restrict__ outp,
                                         int I, int N, int ldw)
{
    int n = blockIdx.x * blockDim.x + threadIdx.x;
    if (n >= N) return;
    float s = 0.f;
    for (int i = 0; i < I; i++) s += bsrc[i] * W[(size_t)i * ldw + n];
    outp[n] = s;
}

__global__ void copy_init_tail_kernel(float* __restrict__ out)
{
    int i = blockIdx.x * blockDim.x + threadIdx.x;
    if (i >= B_ * C_) return;
    int b = i / C_;
    int c = i - b * C_;
    out[(size_t)B_ * T_ * C_ + i] = out[(size_t)b * T_ * C_ + c];
}

// ---------------------------------------------------------------------------
template<int BM, int BN, int AMODE, int CMODE>
static void launch_gemm(const void* A, const __half* Wt, const float* bias,
                        void* C, int M, int N, int K, int Kp, int lda, int ldc,
                        int flags, const float* addin = nullptr, int addld = 0,
                        cudaStream_t st = 0)
{
    const int sbytes = STAGES * (BM + BN) * ASTR * 2;
    cudaFuncSetAttribute(gemm_f16_ldsm<BM, BN, AMODE, CMODE>,
                         cudaFuncAttributeMaxDynamicSharedMemorySize, sbytes);
    dim3 grid((N + BN - 1) / BN, M / BM);
    gemm_f16_ldsm<BM, BN, AMODE, CMODE><<<grid, 256, sbytes, st>>>(
        A, Wt, bias, C, M, N, K, Kp, lda, ldc, flags, addin, addld);
}

template<int BM, int BN, int NSTG>
static void launch_scan(const __half* A, const __half* Wt, const float* bias,
                        __half* C, int N, int K, const float* addin = nullptr)
{
    const int sbytes = NSTG * (BM + BN) * 72 * 2;
    cudaFuncSetAttribute(scan_gemm<BM, BN, NSTG>,
                         cudaFuncAttributeMaxDynamicSharedMemorySize, sbytes);
    dim3 grid(N / BN, 1024 / BM);
    scan_gemm<BM, BN, NSTG><<<grid, 256, sbytes>>>(A, Wt, bias, C, N, K, addin);
}

static void trsp(const float* W, __half* Wt, int K, int N, int Kp, int ldw)
{
    dim3 grid((Kp + 31) / 32, (N + 31) / 32);
    transpose_h_kernel<<<grid, dim3(32, 8)>>>(W, Wt, K, N, Kp, ldw);
}

extern "C" void kernel_launch(void* const* d_in, const int* in_sizes, int n_in,
                              void* d_out, int out_size)
{
    const float* src  = (const float*)d_in[0];
    const float* wi1  = (const float*)d_in[1];
    const float* bi1  = (const float*)d_in[2];
    const float* wi2  = (const float*)d_in[3];
    const float* bi2  = (const float*)d_in[4];
    const float* wi25 = (const float*)d_in[5];
    const float* bi25 = (const float*)d_in[6];
    const float* wi3  = (const float*)d_in[7];
    const float* bi3  = (const float*)d_in[8];
    const float* w1   = (const float*)d_in[9];
    const float* b1   = (const float*)d_in[10];
    const float* w12  = (const float*)d_in[11];
    const float* b12  = (const float*)d_in[12];
    const float* w2   = (const float*)d_in[13];
    const float* b2   = (const float*)d_in[14];
    const float* w22  = (const float*)d_in[15];
    const float* b22  = (const float*)d_in[16];
    const float* w3   = (const float*)d_in[17];
    const float* b3   = (const float*)d_in[18];
    const float* w4   = (const float*)d_in[19];
    const float* b4   = (const float*)d_in[20];
    const float* w4d  = (const float*)d_in[21];
    const float* b4d  = (const float*)d_in[22];

    float* out = (float*)d_out;

    __half *hA, *hB, *hC, *S, *srch, *wh;
    float *bc, *bb, *bbi, *w4c32, *P;
    cudaGetSymbolAddress((void**)&hA,    g_hA);
    cudaGetSymbolAddress((void**)&hB,    g_hB);
    cudaGetSymbolAddress((void**)&hC,    g_hC);
    cudaGetSymbolAddress((void**)&S,     g_S);
    cudaGetSymbolAddress((void**)&srch,  g_srch);
    cudaGetSymbolAddress((void**)&wh,    g_wh);
    cudaGetSymbolAddress((void**)&bc,    g_bc);
    cudaGetSymbolAddress((void**)&bb,    g_bb);
    cudaGetSymbolAddress((void**)&bbi,   g_bbi);
    cudaGetSymbolAddress((void**)&w4c32, g_w4c32);
    cudaGetSymbolAddress((void**)&P,     g_P);

    // Secondary stream + fork/join events (created once; host-side only).
    static cudaStream_t s2 = nullptr;
    static cudaEvent_t evFork = nullptr, evJoin = nullptr;
    static cudaEvent_t evFork2 = nullptr, evJoin2 = nullptr;
    if (!s2) {
        cudaStreamCreateWithFlags(&s2, cudaStreamNonBlocking);
        cudaEventCreateWithFlags(&evFork,  cudaEventDisableTiming);
        cudaEventCreateWithFlags(&evJoin,  cudaEventDisableTiming);
        cudaEventCreateWithFlags(&evFork2, cudaEventDisableTiming);
        cudaEventCreateWithFlags(&evJoin2, cudaEventDisableTiming);
    }

    const float* W1c = w1 + 72 * 2048;   // rows 72..140 of w1

    // ---- prep (main stream) ----
    trsp(wi1,  wh + OFF_WI1T,  3060, 2048, 3072, 2048);
    trsp(wi2,  wh + OFF_WI2T,  2048, 1024, 2048, 1024);
    trsp(wi25, wh + OFF_WI25T, 1024, 512,  1024, 512);
    trsp(wi3,  wh + OFF_WI3T,  512,  69,   512,  69);
    trsp(w1,   wh + OFF_W1ABT, 72,   2048, 96,   2048);
    trsp(w12,  wh + OFF_W12T,  2048, 2048, 2048, 2048);
    trsp(w2,   wh + OFF_W2T,   2048, 1024, 2048, 1024);
    trsp(w22,  wh + OFF_W22T,  1024, 1024, 1024, 1024);
    trsp(w3,   wh + OFF_W3T,   1024, 512,  1024, 512);

    compose_w_f32_kernel<<<512, 128>>>(w4, w4d, w4c32, 512, 512, C_);
    trsp(w4c32, wh + OFF_W4CT, 512, C_, 512, C_);
    compose_w_kernel<<<512, 128>>>(w4c32, W1c, wh + OFF_W41T,  512, C_, 2048);
    compose_w_kernel<<<512, 128>>>(wi3,   W1c, wh + OFF_WI31T, 512, C_, 2048);
    compose_bias_kernel<<<1, 128>>>(b4, w4d, b4d, bc, 512, C_);
    compose_bias_wide_kernel<<<8, 256>>>(bc,  W1c, bb,  C_, 2048, 2048);
    compose_bias_wide_kernel<<<8, 256>>>(bi3, W1c, bbi, C_, 2048, 2048);
    src_round_kernel<<<(B_ * 3072 + 511) / 512, 512>>>(src, srch);

    const int LDO = T_ * C_;

    // ---- FORK: init MLP on s2, P-GEMM on main stream (independent) ----
    cudaEventRecord(evFork, 0);
    cudaStreamWaitEvent(s2, evFork, 0);

    // s2: init MLP: 3060 -> 2048 -> 1024 -> h25(512) -> out[:,0,:] (+ tail copy)
    launch_gemm<64, 128, 0, 0>(srch, wh + OFF_WI1T, bi1, hA,
                               B_, 2048, 3060, 3072, 3072, 2048, 3, nullptr, 0, s2);
    launch_gemm<64, 64, 0, 0>(hA, wh + OFF_WI2T, bi2, hB,
                              B_, 1024, 2048, 2048, 2048, 1024, 3, nullptr, 0, s2);
    launch_gemm<32, 64, 0, 0>(hB, wh + OFF_WI25T, bi25, hC,
                              B_, 512, 1024, 1024, 1024, 512, 2, nullptr, 0, s2);
    launch_gemm<64, 128, 0, 0>(hC, wh + OFF_WI3T, bi3, out,
                               B_, C_, 512, 512, 512, LDO, 0, nullptr, 0, s2);
    if (out_size >= B_ * T_ * C_ + B_ * C_) {
        copy_init_tail_kernel<<<(B_ * C_ + 255) / 256, 256, 0, s2>>>(out);
    }
    cudaEventRecord(evJoin, s2);

    // main: P = concat(src[t-1],src[t]) @ W1ab + b1, all 84 steps at once
    launch_gemm<64, 128, 2, 0>(srch, wh + OFF_W1ABT, b1, P,
                               (T_ - 1) * B_, 2048, 72, 96, 0, 2048, 0);

    // JOIN: scan needs hC (s2) and P (main)
    cudaStreamWaitEvent(0, evJoin, 0);

    // ---- scan: 84 steps x 5 GEMMs, R9 fast path ----
    const int T_SPLIT = 44;   // steps 1..43 scattered early on s2
    for (int t = 1; t < T_; t++) {
        const __half* sPrev = (t == 1) ? hC : S + (size_t)(t - 2) * B_ * H_;
        const __half* Wl1   = (t == 1) ? (wh + OFF_WI31T) : (wh + OFF_W41T);
        const float*  bl1   = (t == 1) ? bbi : bb;

        launch_scan< 64, 128, 3>(sPrev, Wl1, bl1, hA, 2048, 512,
                                 P + (size_t)(t - 1) * B_ * 2048);
        launch_scan<128, 128, 2>(hA, wh + OFF_W12T, b12, hB, 2048, 2048);
        launch_scan< 64, 128, 3>(hB, wh + OFF_W2T,  b2,  hA, 1024, 2048);
        launch_scan< 64, 128, 3>(hA, wh + OFF_W22T, b22, hB, 1024, 1024);
        launch_scan< 64,  64, 3>(hB, wh + OFF_W3T,  b3,
                                 S + (size_t)(t - 1) * B_ * H_, 512, 1024);

        if (t == T_SPLIT - 1) {
            // FORK2: scatter out[:,1..43,:] on s2, overlapping remaining scan
            cudaEventRecord(evFork2, 0);
            cudaStreamWaitEvent(s2, evFork2, 0);
            launch_gemm<64, 128, 0, 1>(S, wh + OFF_W4CT, bc, out,
                                       (T_SPLIT - 1) * B_, C_, 512, 512, 512,
                                       LDO, 0, nullptr, 0, s2);
            cudaEventRecord(evJoin2, s2);
        }
    }

    // ---- remainder scatter: out[:,44..84,:] (time base shifted by T_SPLIT-1)
    launch_gemm<64, 128, 0, 1>(S + (size_t)(T_SPLIT - 1) * B_ * H_,
                               wh + OFF_W4CT, bc, out + (size_t)(T_SPLIT - 1) * C_,
                               (T_ - T_SPLIT) * B_, C_, 512, 512, 512, LDO, 0);

    // JOIN2: ensure the early scatter finished before kernel_launch returns work
    cudaStreamWaitEvent(0, evJoin2, 0);
}